// round 10
// baseline (speedup 1.0000x reference)
#include <cuda_runtime.h>
#include <math.h>

#define NBLOCKS 128
#define NTHREADS 256
#define SAMP 8
#define CC 64
#define HH 128
#define MAX_IT 500
#define TOLV 1e-3f

// Padded rows: stride ≡ 2 (mod 32) -> conflict-free 64-bit LDS in BOTH the
// strided (output-dim across lanes) and contiguous access patterns.
struct Smem {
    float wz1[HH][HH + 2];   // clipped Wz1, [j][k], row stride 130
    float wy0[HH][CC + 2];   // [j][c], row stride 66
    float wy1[HH][CC + 2];   // [j][c]
    float wz2[HH];           // clipped
    float wy2[CC];
    float by0[HH];
    float by1[HH];
    float by2[2];
    float z [SAMP][CC];
    float x1[SAMP][CC];
    float h0v[SAMP][HH];     // h0 in fwd, reused as v in bwd
    float s0 [SAMP][HH];     // sigmoid(a0)
    float s1u[SAMP][HH];     // sigmoid(a1) in fwd, reused as u1 in bwd
    float a2  [SAMP];
    float s2  [SAMP];
    float nrm2[SAMP];
};

__device__ unsigned int g_bar_count = 0;
__device__ unsigned int g_bar_gen   = 0;
__device__ float        g_err[MAX_IT];

__device__ __forceinline__ float sp_f(float x) {  // softplus, stable
    return fmaxf(x, 0.0f) + log1pf(__expf(-fabsf(x)));
}
__device__ __forceinline__ float sg_f(float x) {  // sigmoid
    return __fdividef(1.0f, 1.0f + __expf(-x));
}

// Sense-reversal grid barrier. Safe: grid = 128 blocks, 1 block/SM (152KB smem),
// single wave on 148 SMs -> all blocks co-resident.
__device__ __forceinline__ void grid_barrier() {
    __syncthreads();
    if (threadIdx.x == 0) {
        __threadfence();
        unsigned int gen = *((volatile unsigned int*)&g_bar_gen);
        if (atomicAdd(&g_bar_count, 1u) == (unsigned)(NBLOCKS - 1)) {
            atomicExch(&g_bar_count, 0u);
            __threadfence();
            atomicAdd(&g_bar_gen, 1u);
        } else {
            while (*((volatile unsigned int*)&g_bar_gen) == gen) __nanosleep(32);
        }
    }
    __syncthreads();
}

extern "C" __global__ void __launch_bounds__(NTHREADS, 1)
blnn_kernel(const float* __restrict__ x,   const float* __restrict__ Wy0,
            const float* __restrict__ by0, const float* __restrict__ Wy1,
            const float* __restrict__ by1, const float* __restrict__ Wz1,
            const float* __restrict__ Wy2, const float* __restrict__ by2,
            const float* __restrict__ Wz2, float* __restrict__ out)
{
    extern __shared__ __align__(16) float smem_raw[];
    Smem* sm = (Smem*)smem_raw;
    const int tid = threadIdx.x;
    const int bx  = blockIdx.x;

    // ---- load weights into SMEM (clip Wz* at 0) ----
    for (int idx = tid; idx < HH * HH; idx += NTHREADS) {
        int j = idx >> 7, k = idx & (HH - 1);
        sm->wz1[j][k] = fmaxf(Wz1[idx], 0.0f);
    }
    for (int idx = tid; idx < HH * CC; idx += NTHREADS) {
        int j = idx >> 6, c = idx & (CC - 1);
        sm->wy0[j][c] = Wy0[idx];
        sm->wy1[j][c] = Wy1[idx];
    }
    if (tid < HH) {
        sm->wz2[tid] = fmaxf(Wz2[tid], 0.0f);
        sm->by0[tid] = by0[tid];
        sm->by1[tid] = by1[tid];
    }
    if (tid < CC) sm->wy2[tid] = Wy2[tid];
    if (tid == 0) sm->by2[0] = by2[0];

    const int sbase = bx * SAMP;
    for (int idx = tid; idx < SAMP * CC; idx += NTHREADS) {
        sm->z [idx >> 6][idx & 63] = x[sbase * CC + idx];
        sm->x1[idx >> 6][idx & 63] = 1.0f;   // x1_0 = ones
    }
    // zero our stripe of the per-iteration err accumulator (bypass L1)
    if (tid == 0) {
        for (int idx = bx; idx < MAX_IT; idx += NBLOCKS)
            *((volatile float*)&g_err[idx]) = 0.0f;
    }
    grid_barrier();

    // thread mappings
    const int j    = tid & (HH - 1);   // stages 1/2/4: feature j, 4 samples each
    const int sgrp = tid >> 7;         // 0/1 -> samples 4*sgrp..4*sgrp+3
    const int kg   = tid & 63;         // stage 5: k pair 2*kg, samples s5 & s5+4
    const int s5   = tid >> 6;
    const int cg   = tid & 31;         // stage 6: c pair 2*cg, one sample s6
    const int s6   = tid >> 5;
    const int lane = tid & 31;
    const int warp = tid >> 5;

    int it = 0;
    for (; it < MAX_IT; ++it) {
        if (tid < SAMP) sm->a2[tid] = 0.0f;

        // ---- stage 1: a0 = Wy0 x1 + by0 ; h0 = sp(a0), s0 = sg(a0) ----
        {
            float acc[4];
            #pragma unroll
            for (int t = 0; t < 4; t++) acc[t] = sm->by0[j];
            #pragma unroll 4
            for (int c = 0; c < CC; c += 2) {
                float2 w = *(const float2*)&sm->wy0[j][c];
                #pragma unroll
                for (int t = 0; t < 4; t++) {
                    float2 xv = *(const float2*)&sm->x1[4 * sgrp + t][c];
                    acc[t] += w.x * xv.x + w.y * xv.y;
                }
            }
            #pragma unroll
            for (int t = 0; t < 4; t++) {
                int s = 4 * sgrp + t;
                sm->h0v[s][j] = sp_f(acc[t]);
                sm->s0 [s][j] = sg_f(acc[t]);
            }
        }
        __syncthreads();

        // ---- stage 2+3: a1 = Wz1p h0 + Wy1 x1 + by1 ; s1 ; partial a2 ----
        {
            float acc[4];
            #pragma unroll
            for (int t = 0; t < 4; t++) acc[t] = sm->by1[j];
            #pragma unroll 4
            for (int k = 0; k < HH; k += 2) {
                float2 w = *(const float2*)&sm->wz1[j][k];
                #pragma unroll
                for (int t = 0; t < 4; t++) {
                    float2 h = *(const float2*)&sm->h0v[4 * sgrp + t][k];
                    acc[t] += w.x * h.x + w.y * h.y;
                }
            }
            #pragma unroll 4
            for (int c = 0; c < CC; c += 2) {
                float2 w = *(const float2*)&sm->wy1[j][c];
                #pragma unroll
                for (int t = 0; t < 4; t++) {
                    float2 xv = *(const float2*)&sm->x1[4 * sgrp + t][c];
                    acc[t] += w.x * xv.x + w.y * xv.y;
                }
            }
            float p[4];
            float wz2j = sm->wz2[j];
            #pragma unroll
            for (int t = 0; t < 4; t++) {
                int s = 4 * sgrp + t;
                sm->s1u[s][j] = sg_f(acc[t]);
                p[t] = sp_f(acc[t]) * wz2j;          // h1_j * Wz2p_j
            }
            #pragma unroll
            for (int off = 16; off; off >>= 1) {
                #pragma unroll
                for (int t = 0; t < 4; t++)
                    p[t] += __shfl_down_sync(0xffffffffu, p[t], off);
            }
            if (lane == 0) {
                #pragma unroll
                for (int t = 0; t < 4; t++)
                    atomicAdd(&sm->a2[4 * sgrp + t], p[t]);
            }
        }
        __syncthreads();

        // ---- stage 3 finalize: a2 += Wy2·x1 + by2 ; s2 = sg(a2). warp w -> sample w
        {
            float part = sm->wy2[lane]      * sm->x1[warp][lane]
                       + sm->wy2[lane + 32] * sm->x1[warp][lane + 32];
            #pragma unroll
            for (int off = 16; off; off >>= 1)
                part += __shfl_down_sync(0xffffffffu, part, off);
            if (lane == 0)
                sm->s2[warp] = sg_f(sm->a2[warp] + part + sm->by2[0]);
        }
        __syncthreads();

        // ---- stage 4: u1 = s2 * Wz2p * s1 (in place) ----
        {
            float wz2j = sm->wz2[j];
            #pragma unroll
            for (int t = 0; t < 4; t++) {
                int s = 4 * sgrp + t;
                sm->s1u[s][j] *= sm->s2[s] * wz2j;
            }
        }
        __syncthreads();

        // ---- stage 5: v_k = (sum_j u1_j Wz1p[j][k]) * s0_k  (into h0v) ----
        {
            int k0 = 2 * kg;
            float aAx = 0.f, aAy = 0.f, aBx = 0.f, aBy = 0.f;
            #pragma unroll 4
            for (int jj = 0; jj < HH; jj++) {
                float2 w = *(const float2*)&sm->wz1[jj][k0];
                float uA = sm->s1u[s5][jj];
                float uB = sm->s1u[s5 + 4][jj];
                aAx += w.x * uA; aAy += w.y * uA;
                aBx += w.x * uB; aBy += w.y * uB;
            }
            sm->h0v[s5][k0]         = aAx * sm->s0[s5][k0];
            sm->h0v[s5][k0 + 1]     = aAy * sm->s0[s5][k0 + 1];
            sm->h0v[s5 + 4][k0]     = aBx * sm->s0[s5 + 4][k0];
            sm->h0v[s5 + 4][k0 + 1] = aBy * sm->s0[s5 + 4][k0 + 1];
        }
        __syncthreads();

        // ---- stage 6: g = v Wy0 + u1 Wy1 + s2 Wy2 + x1 ; update x1 ; norm ----
        {
            int c0 = 2 * cg;
            float gx = 0.f, gy = 0.f;
            #pragma unroll 4
            for (int k = 0; k < HH; k++) {
                float2 w0 = *(const float2*)&sm->wy0[k][c0];
                float2 w1 = *(const float2*)&sm->wy1[k][c0];
                float vv = sm->h0v[s6][k];
                float uu = sm->s1u[s6][k];
                gx += w0.x * vv + w1.x * uu;
                gy += w0.y * vv + w1.y * uu;
            }
            float s2v = sm->s2[s6];
            float x1x = sm->x1[s6][c0], x1y = sm->x1[s6][c0 + 1];
            gx += s2v * sm->wy2[c0]     + x1x;
            gy += s2v * sm->wy2[c0 + 1] + x1y;
            float dx = sm->z[s6][c0]     - gx;
            float dy = sm->z[s6][c0 + 1] - gy;
            float step = __fdividef(2.0f, (float)(it + 1));
            sm->x1[s6][c0]     = x1x + step * dx;
            sm->x1[s6][c0 + 1] = x1y + step * dy;
            float d2 = dx * dx + dy * dy;
            #pragma unroll
            for (int off = 16; off; off >>= 1)
                d2 += __shfl_down_sync(0xffffffffu, d2, off);
            if (lane == 0) sm->nrm2[s6] = d2;   // exactly one warp per sample
        }
        __syncthreads();

        if (tid == 0) {
            float sum = 0.f;
            #pragma unroll
            for (int s = 0; s < SAMP; s++) sum += sqrtf(sm->nrm2[s]);
            atomicAdd(&g_err[it], sum);
        }
        grid_barrier();

        float tot = *((volatile float*)&g_err[it]);
        if (tot < TOLV * 1024.0f) { ++it; break; }   // done flips; rest are no-ops
    }

    // ---- output: x1 + CONVEX*z ----
    for (int idx = tid; idx < SAMP * CC; idx += NTHREADS) {
        int s = idx >> 6, c = idx & 63;
        out[sbase * CC + idx] = sm->x1[s][c] + sm->z[s][c];
    }
}

extern "C" void kernel_launch(void* const* d_in, const int* in_sizes, int n_in,
                              void* d_out, int out_size) {
    (void)in_sizes; (void)n_in; (void)out_size;
    cudaFuncSetAttribute(blnn_kernel,
                         cudaFuncAttributeMaxDynamicSharedMemorySize,
                         (int)sizeof(Smem));
    blnn_kernel<<<NBLOCKS, NTHREADS, sizeof(Smem)>>>(
        (const float*)d_in[0], (const float*)d_in[1], (const float*)d_in[2],
        (const float*)d_in[3], (const float*)d_in[4], (const float*)d_in[5],
        (const float*)d_in[6], (const float*)d_in[7], (const float*)d_in[8],
        (float*)d_out);
}

// round 11
// speedup vs baseline: 1.3231x; 1.3231x over previous
#include <cuda_runtime.h>
#include <math.h>

#define NBLOCKS 128
#define NTHREADS 256
#define SAMP 8
#define CC 64
#define HH 128
#define MAX_IT 500
#define TOLV 1e-3f
#define WZ1_S 132   // row stride (floats) for wz1: mult of 4, ≡4 mod 32 -> LDS.128 conflict-free
#define WY_S  68    // row stride for wy0/wy1

typedef unsigned long long u64t;

struct __align__(16) Smem {
    float wz1[HH * WZ1_S];     // clipped Wz1 [j][k]
    float wy0[HH * WY_S];      // [j][c]
    float wy1[HH * WY_S];      // [j][c]
    float wz2[HH];             // clipped
    float wy2[CC];
    float by0[HH];
    float by1[HH];
    float z  [SAMP][CC];
    float x1 [SAMP][CC];
    float h0v[SAMP][HH];       // h0 fwd, v~ bwd
    float s0 [SAMP][HH];       // sigmoid(a0)
    float s1u[SAMP][HH];       // u~ = wz2 * sigmoid(a1)  (s2 folded at epilogue)
    float scratch[2048];       // stage partials: [s][128] or [q][s][64]
    float a2  [SAMP];
    float s2  [SAMP];
    float nrm2[SAMP];
    float by2;
    int   flag;
};

__device__ unsigned int g_bar_count = 0;
__device__ unsigned int g_bar_gen   = 0;
__device__ float        g_err[MAX_IT];
__device__ unsigned int g_cnt[MAX_IT];

__device__ __forceinline__ u64t pk2(float lo, float hi) {
    u64t r; asm("mov.b64 %0, {%1,%2};" : "=l"(r) : "f"(lo), "f"(hi)); return r;
}
__device__ __forceinline__ void fma2(u64t& d, u64t a, u64t b) {
    asm("fma.rn.f32x2 %0, %1, %2, %0;" : "+l"(d) : "l"(a), "l"(b));
}
__device__ __forceinline__ float rsum2(u64t a) {
    float lo, hi; asm("mov.b64 {%0,%1}, %2;" : "=f"(lo), "=f"(hi) : "l"(a));
    return lo + hi;
}

// classic sense-reversal barrier (used once at startup; persists across graph replays)
__device__ __forceinline__ void grid_barrier() {
    __syncthreads();
    if (threadIdx.x == 0) {
        __threadfence();
        unsigned int gen = *((volatile unsigned int*)&g_bar_gen);
        if (atomicAdd(&g_bar_count, 1u) == (unsigned)(NBLOCKS - 1)) {
            atomicExch(&g_bar_count, 0u);
            __threadfence();
            atomicAdd(&g_bar_gen, 1u);
        } else {
            while (*((volatile unsigned int*)&g_bar_gen) == gen) __nanosleep(32);
        }
    }
    __syncthreads();
}

extern "C" __global__ void __launch_bounds__(NTHREADS, 1)
blnn_kernel(const float* __restrict__ x,   const float* __restrict__ Wy0,
            const float* __restrict__ by0, const float* __restrict__ Wy1,
            const float* __restrict__ by1, const float* __restrict__ Wz1,
            const float* __restrict__ Wy2, const float* __restrict__ by2,
            const float* __restrict__ Wz2, float* __restrict__ out)
{
    extern __shared__ __align__(16) float smem_raw[];
    Smem* sm = (Smem*)smem_raw;
    const int tid  = threadIdx.x;
    const int bx   = blockIdx.x;
    const int lane = tid & 31;
    const int warp = tid >> 5;

    // ---- weights -> SMEM (padded strides, clip Wz* at 0) ----
    for (int idx = tid; idx < HH * HH; idx += NTHREADS) {
        int jj = idx >> 7, kk = idx & (HH - 1);
        sm->wz1[jj * WZ1_S + kk] = fmaxf(Wz1[idx], 0.0f);
    }
    for (int idx = tid; idx < HH * CC; idx += NTHREADS) {
        int jj = idx >> 6, c2 = idx & (CC - 1);
        sm->wy0[jj * WY_S + c2] = Wy0[idx];
        sm->wy1[jj * WY_S + c2] = Wy1[idx];
    }
    if (tid < HH) {
        sm->wz2[tid] = fmaxf(Wz2[tid], 0.0f);
        sm->by0[tid] = by0[tid];
        sm->by1[tid] = by1[tid];
    }
    if (tid < CC) sm->wy2[tid] = Wy2[tid];
    if (tid == 0) sm->by2 = by2[0];

    const int sbase = bx * SAMP;
    for (int idx = tid; idx < SAMP * CC; idx += NTHREADS) {
        sm->z [idx >> 6][idx & 63] = x[sbase * CC + idx];
        sm->x1[idx >> 6][idx & 63] = 1.0f;
    }
    // re-zero our stripe of the per-iteration accumulators (graph replays!)
    if (tid == 0) {
        for (int idx = bx; idx < MAX_IT; idx += NBLOCKS) {
            *((volatile float*)&g_err[idx]) = 0.0f;
            *((volatile unsigned int*)&g_cnt[idx]) = 0u;
        }
    }
    grid_barrier();

    const int j  = tid & (HH - 1);   // stages 1/2/5: feature / k index
    const int hh = tid >> 7;         // reduction half
    const int c6 = tid & (CC - 1);   // stage 6: output c
    const int q6 = tid >> 6;         // stage 6: k-quarter

    int it = 0;
    for (; it < MAX_IT; ++it) {
        if (tid < SAMP) { sm->a2[tid] = 0.0f; sm->nrm2[tid] = 0.0f; }

        // ================= stage 1: a0 = Wy0 x1 + by0 =================
        {
            u64t acc[SAMP];
            #pragma unroll
            for (int s = 0; s < SAMP; s++) acc[s] = 0ull;
            const float* wrow = &sm->wy0[j * WY_S + 32 * hh];
            const int cb = 32 * hh;
            #pragma unroll 2
            for (int cq = 0; cq < 32; cq += 4) {
                ulonglong2 w = *(const ulonglong2*)(wrow + cq);
                #pragma unroll
                for (int s = 0; s < SAMP; s++) {
                    ulonglong2 xv = *(const ulonglong2*)&sm->x1[s][cb + cq];
                    fma2(acc[s], w.x, xv.x);
                    fma2(acc[s], w.y, xv.y);
                }
            }
            const int so = 4 * (1 - hh);
            #pragma unroll
            for (int t = 0; t < 4; t++)
                sm->scratch[(so + t) * HH + j] = rsum2(acc[so + t]);
            __syncthreads();
            const int sm0 = 4 * hh;
            #pragma unroll
            for (int t = 0; t < 4; t++) {
                int s = sm0 + t;
                float a   = rsum2(acc[s]) + sm->scratch[s * HH + j] + sm->by0[j];
                float e   = __expf(-fabsf(a));
                float inv = __fdividef(1.0f, 1.0f + e);
                sm->h0v[s][j] = fmaxf(a, 0.0f) + __logf(1.0f + e);
                sm->s0 [s][j] = (a >= 0.0f) ? inv : e * inv;
            }
        }
        __syncthreads();

        // ====== stage 2: a1 = Wz1p h0 + Wy1 x1 + by1 ; u~ ; a2 partial ======
        {
            u64t acc[SAMP];
            #pragma unroll
            for (int s = 0; s < SAMP; s++) acc[s] = 0ull;
            const float* wzrow = &sm->wz1[j * WZ1_S + 64 * hh];
            const int kb = 64 * hh;
            #pragma unroll 2
            for (int kq = 0; kq < 64; kq += 4) {
                ulonglong2 w = *(const ulonglong2*)(wzrow + kq);
                #pragma unroll
                for (int s = 0; s < SAMP; s++) {
                    ulonglong2 hv = *(const ulonglong2*)&sm->h0v[s][kb + kq];
                    fma2(acc[s], w.x, hv.x);
                    fma2(acc[s], w.y, hv.y);
                }
            }
            const float* wyrow = &sm->wy1[j * WY_S + 32 * hh];
            const int cb = 32 * hh;
            #pragma unroll 2
            for (int cq = 0; cq < 32; cq += 4) {
                ulonglong2 w = *(const ulonglong2*)(wyrow + cq);
                #pragma unroll
                for (int s = 0; s < SAMP; s++) {
                    ulonglong2 xv = *(const ulonglong2*)&sm->x1[s][cb + cq];
                    fma2(acc[s], w.x, xv.x);
                    fma2(acc[s], w.y, xv.y);
                }
            }
            const int so = 4 * (1 - hh);
            #pragma unroll
            for (int t = 0; t < 4; t++)
                sm->scratch[(so + t) * HH + j] = rsum2(acc[so + t]);
            __syncthreads();
            const float wz2j = sm->wz2[j];
            const int sm0 = 4 * hh;
            float pv[4];
            #pragma unroll
            for (int t = 0; t < 4; t++) {
                int s = sm0 + t;
                float a   = rsum2(acc[s]) + sm->scratch[s * HH + j] + sm->by1[j];
                float e   = __expf(-fabsf(a));
                float inv = __fdividef(1.0f, 1.0f + e);
                float sg  = (a >= 0.0f) ? inv : e * inv;
                sm->s1u[s][j] = wz2j * sg;                               // u~
                pv[t] = wz2j * (fmaxf(a, 0.0f) + __logf(1.0f + e));      // wz2*h1
            }
            #pragma unroll
            for (int off = 16; off; off >>= 1) {
                #pragma unroll
                for (int t = 0; t < 4; t++)
                    pv[t] += __shfl_down_sync(0xffffffffu, pv[t], off);
            }
            if (lane == 0) {
                #pragma unroll
                for (int t = 0; t < 4; t++)
                    atomicAdd(&sm->a2[sm0 + t], pv[t]);
            }
        }
        __syncthreads();

        // ============ stage 3: s2 = sigmoid(a2 + Wy2.x1 + by2) ============
        {
            float part = sm->wy2[lane]      * sm->x1[warp][lane]
                       + sm->wy2[lane + 32] * sm->x1[warp][lane + 32];
            #pragma unroll
            for (int off = 16; off; off >>= 1)
                part += __shfl_down_sync(0xffffffffu, part, off);
            if (lane == 0) {
                float a   = sm->a2[warp] + part + sm->by2;
                float e   = __expf(-fabsf(a));
                float inv = __fdividef(1.0f, 1.0f + e);
                sm->s2[warp] = (a >= 0.0f) ? inv : e * inv;
            }
        }
        __syncthreads();

        // ========= stage 5: v~_k = s0_k * sum_j u~_j wz1[j][k] =========
        {
            u64t acc[SAMP];
            #pragma unroll
            for (int s = 0; s < SAMP; s++) acc[s] = 0ull;
            const int jb = 64 * hh;
            #pragma unroll 2
            for (int jq = 0; jq < 64; jq += 4) {
                const float* col = &sm->wz1[(jb + jq) * WZ1_S + j];
                u64t wA = pk2(col[0],         col[WZ1_S]);
                u64t wB = pk2(col[2 * WZ1_S], col[3 * WZ1_S]);
                #pragma unroll
                for (int s = 0; s < SAMP; s++) {
                    ulonglong2 uv = *(const ulonglong2*)&sm->s1u[s][jb + jq];
                    fma2(acc[s], wA, uv.x);
                    fma2(acc[s], wB, uv.y);
                }
            }
            const int so = 4 * (1 - hh);
            #pragma unroll
            for (int t = 0; t < 4; t++)
                sm->scratch[(so + t) * HH + j] = rsum2(acc[so + t]);
            __syncthreads();
            const int sm0 = 4 * hh;
            #pragma unroll
            for (int t = 0; t < 4; t++) {
                int s = sm0 + t;
                sm->h0v[s][j] = (rsum2(acc[s]) + sm->scratch[s * HH + j]) * sm->s0[s][j];
            }
        }
        __syncthreads();

        // == stage 6: g = s2*(v~ Wy0 + u~ Wy1 + Wy2) + x1 ; update ; norm ==
        {
            u64t acc[SAMP];
            #pragma unroll
            for (int s = 0; s < SAMP; s++) acc[s] = 0ull;
            const int kb = 32 * q6;
            #pragma unroll 2
            for (int kq = 0; kq < 32; kq += 4) {
                int k = kb + kq;
                const float* c0 = &sm->wy0[k * WY_S + c6];
                const float* c1 = &sm->wy1[k * WY_S + c6];
                u64t w0A = pk2(c0[0],        c0[WY_S]);
                u64t w0B = pk2(c0[2 * WY_S], c0[3 * WY_S]);
                u64t w1A = pk2(c1[0],        c1[WY_S]);
                u64t w1B = pk2(c1[2 * WY_S], c1[3 * WY_S]);
                #pragma unroll
                for (int s = 0; s < SAMP; s++) {
                    ulonglong2 vv = *(const ulonglong2*)&sm->h0v[s][k];
                    ulonglong2 uu = *(const ulonglong2*)&sm->s1u[s][k];
                    fma2(acc[s], w0A, vv.x);
                    fma2(acc[s], w0B, vv.y);
                    fma2(acc[s], w1A, uu.x);
                    fma2(acc[s], w1B, uu.y);
                }
            }
            #pragma unroll
            for (int s = 0; s < SAMP; s++)
                sm->scratch[q6 * 512 + s * CC + c6] = rsum2(acc[s]);
            __syncthreads();

            const float step = __fdividef(2.0f, (float)(it + 1));
            float d2v[2];
            #pragma unroll
            for (int t = 0; t < 2; t++) {
                int s = q6 + 4 * t;
                float g = sm->scratch[0 * 512 + s * CC + c6]
                        + sm->scratch[1 * 512 + s * CC + c6]
                        + sm->scratch[2 * 512 + s * CC + c6]
                        + sm->scratch[3 * 512 + s * CC + c6];
                float x1v = sm->x1[s][c6];
                g = sm->s2[s] * (g + sm->wy2[c6]) + x1v;
                float d = sm->z[s][c6] - g;
                sm->x1[s][c6] = x1v + step * d;
                d2v[t] = d * d;
            }
            #pragma unroll
            for (int off = 16; off; off >>= 1) {
                d2v[0] += __shfl_down_sync(0xffffffffu, d2v[0], off);
                d2v[1] += __shfl_down_sync(0xffffffffu, d2v[1], off);
            }
            if (lane == 0) {
                atomicAdd(&sm->nrm2[q6],     d2v[0]);
                atomicAdd(&sm->nrm2[q6 + 4], d2v[1]);
            }
        }
        __syncthreads();

        // ==== merged error reduction + grid barrier (per-iter slots) ====
        if (tid == 0) {
            float sum = 0.0f;
            #pragma unroll
            for (int s = 0; s < SAMP; s++) sum += sqrtf(sm->nrm2[s]);
            atomicAdd(&g_err[it], sum);
            __threadfence();
            unsigned int n = atomicAdd(&g_cnt[it], 1u) + 1u;
            while (n < (unsigned)NBLOCKS) {
                __nanosleep(32);
                n = *((volatile unsigned int*)&g_cnt[it]);
            }
            sm->flag = (*((volatile float*)&g_err[it]) < TOLV * 1024.0f) ? 1 : 0;
        }
        __syncthreads();
        if (sm->flag) break;   // done flips; remaining iterations are no-ops
    }

    // ---- output: x1 + CONVEX*z ----
    for (int idx = tid; idx < SAMP * CC; idx += NTHREADS) {
        int s = idx >> 6, c2 = idx & 63;
        out[sbase * CC + idx] = sm->x1[s][c2] + sm->z[s][c2];
    }
}

extern "C" void kernel_launch(void* const* d_in, const int* in_sizes, int n_in,
                              void* d_out, int out_size) {
    (void)in_sizes; (void)n_in; (void)out_size;
    cudaFuncSetAttribute(blnn_kernel,
                         cudaFuncAttributeMaxDynamicSharedMemorySize,
                         (int)sizeof(Smem));
    blnn_kernel<<<NBLOCKS, NTHREADS, sizeof(Smem)>>>(
        (const float*)d_in[0], (const float*)d_in[1], (const float*)d_in[2],
        (const float*)d_in[3], (const float*)d_in[4], (const float*)d_in[5],
        (const float*)d_in[6], (const float*)d_in[7], (const float*)d_in[8],
        (float*)d_out);
}

// round 12
// speedup vs baseline: 1.4564x; 1.1008x over previous
#include <cuda_runtime.h>
#include <math.h>

#define NBLOCKS 128
#define NTHREADS 512
#define SAMP 8
#define CC 64
#define HH 128
#define MAX_IT 500
#define TOLV 1e-3f
#define WZ1_S 132   // row stride (floats): mult of 4, ≡4 mod 32 -> LDS.128 conflict-free
#define WY_S  68

typedef unsigned long long u64t;

struct __align__(16) Smem {
    float wz1[HH * WZ1_S];     // clipped Wz1 [j][k]
    float wy0[HH * WY_S];      // [j][c]
    float wy1[HH * WY_S];      // [j][c]
    float wz2[HH];             // clipped
    float wy2[CC];
    float by0[HH];
    float by1[HH];
    float z  [SAMP][CC];
    float x1 [SAMP][CC];
    float h0v[SAMP][HH];       // h0 fwd, v~ bwd
    float s0 [SAMP][HH];       // sigmoid(a0)
    float s1u[SAMP][HH];       // u~ = wz2 * sigmoid(a1)
    float scratch[4096];       // stage partials: [q][s][128] or [o][s][64]
    float a2  [SAMP];
    float s2  [SAMP];
    float nrm2[SAMP];
    float by2;
    int   flag;
};

__device__ unsigned int g_bar_count = 0;
__device__ unsigned int g_bar_gen   = 0;
__device__ float        g_err[MAX_IT];
__device__ unsigned int g_cnt[MAX_IT];

__device__ __forceinline__ u64t pk2(float lo, float hi) {
    u64t r; asm("mov.b64 %0, {%1,%2};" : "=l"(r) : "f"(lo), "f"(hi)); return r;
}
__device__ __forceinline__ void fma2(u64t& d, u64t a, u64t b) {
    asm("fma.rn.f32x2 %0, %1, %2, %0;" : "+l"(d) : "l"(a), "l"(b));
}
__device__ __forceinline__ float rsum2(u64t a) {
    float lo, hi; asm("mov.b64 {%0,%1}, %2;" : "=f"(lo), "=f"(hi) : "l"(a));
    return lo + hi;
}

// startup-only sense-reversal barrier (device globals persist across graph replays)
__device__ __forceinline__ void grid_barrier() {
    __syncthreads();
    if (threadIdx.x == 0) {
        __threadfence();
        unsigned int gen = *((volatile unsigned int*)&g_bar_gen);
        if (atomicAdd(&g_bar_count, 1u) == (unsigned)(NBLOCKS - 1)) {
            atomicExch(&g_bar_count, 0u);
            __threadfence();
            atomicAdd(&g_bar_gen, 1u);
        } else {
            while (*((volatile unsigned int*)&g_bar_gen) == gen) __nanosleep(32);
        }
    }
    __syncthreads();
}

extern "C" __global__ void __launch_bounds__(NTHREADS, 1)
blnn_kernel(const float* __restrict__ x,   const float* __restrict__ Wy0,
            const float* __restrict__ by0, const float* __restrict__ Wy1,
            const float* __restrict__ by1, const float* __restrict__ Wz1,
            const float* __restrict__ Wy2, const float* __restrict__ by2,
            const float* __restrict__ Wz2, float* __restrict__ out)
{
    extern __shared__ __align__(16) float smem_raw[];
    Smem* sm = (Smem*)smem_raw;
    const int tid  = threadIdx.x;
    const int bx   = blockIdx.x;
    const int lane = tid & 31;
    const int warp = tid >> 5;

    // ---- weights -> SMEM (padded strides, clip Wz* at 0) ----
    for (int idx = tid; idx < HH * HH; idx += NTHREADS) {
        int jj = idx >> 7, kk = idx & (HH - 1);
        sm->wz1[jj * WZ1_S + kk] = fmaxf(Wz1[idx], 0.0f);
    }
    for (int idx = tid; idx < HH * CC; idx += NTHREADS) {
        int jj = idx >> 6, c2 = idx & (CC - 1);
        sm->wy0[jj * WY_S + c2] = Wy0[idx];
        sm->wy1[jj * WY_S + c2] = Wy1[idx];
    }
    if (tid < HH) {
        sm->wz2[tid] = fmaxf(Wz2[tid], 0.0f);
        sm->by0[tid] = by0[tid];
        sm->by1[tid] = by1[tid];
    }
    if (tid < CC) sm->wy2[tid] = Wy2[tid];
    if (tid == 0) sm->by2 = by2[0];

    const int sbase = bx * SAMP;
    for (int idx = tid; idx < SAMP * CC; idx += NTHREADS) {
        sm->z [idx >> 6][idx & 63] = x[sbase * CC + idx];
        sm->x1[idx >> 6][idx & 63] = 1.0f;
    }
    // re-zero our stripe of the per-iteration accumulators (graph replays!)
    if (tid == 0) {
        for (int idx = bx; idx < MAX_IT; idx += NBLOCKS) {
            *((volatile float*)&g_err[idx]) = 0.0f;
            *((volatile unsigned int*)&g_cnt[idx]) = 0u;
        }
    }
    grid_barrier();

    const int j  = tid & (HH - 1);   // stages 1/2/5: output feature index
    const int q  = tid >> 7;         // 0..3: reduction quarter
    const int c6 = tid & (CC - 1);   // stage 6: output c
    const int o6 = tid >> 6;         // 0..7: stage 6 reduction eighth

    int it = 0;
    for (; it < MAX_IT; ++it) {
        if (tid < SAMP) { sm->a2[tid] = 0.0f; sm->nrm2[tid] = 0.0f; }

        // ================= stage 1: a0 = Wy0 x1 + by0 =================
        {
            u64t acc[SAMP];
            #pragma unroll
            for (int s = 0; s < SAMP; s++) acc[s] = 0ull;
            const float* wrow = &sm->wy0[j * WY_S + 16 * q];
            const int cb = 16 * q;
            #pragma unroll
            for (int cq = 0; cq < 16; cq += 4) {
                ulonglong2 w = *(const ulonglong2*)(wrow + cq);
                #pragma unroll
                for (int s = 0; s < SAMP; s++) {
                    ulonglong2 xv = *(const ulonglong2*)&sm->x1[s][cb + cq];
                    fma2(acc[s], w.x, xv.x);
                    fma2(acc[s], w.y, xv.y);
                }
            }
            #pragma unroll
            for (int s = 0; s < SAMP; s++)
                sm->scratch[q * 1024 + s * HH + j] = rsum2(acc[s]);
            __syncthreads();
            #pragma unroll
            for (int t = 0; t < 2; t++) {
                int s = 2 * q + t;
                float a = sm->scratch[0 * 1024 + s * HH + j]
                        + sm->scratch[1 * 1024 + s * HH + j]
                        + sm->scratch[2 * 1024 + s * HH + j]
                        + sm->scratch[3 * 1024 + s * HH + j] + sm->by0[j];
                float e   = __expf(-fabsf(a));
                float inv = __fdividef(1.0f, 1.0f + e);
                sm->h0v[s][j] = fmaxf(a, 0.0f) + __logf(1.0f + e);
                sm->s0 [s][j] = (a >= 0.0f) ? inv : e * inv;
            }
        }
        __syncthreads();

        // ====== stage 2: a1 = Wz1p h0 + Wy1 x1 + by1 ; u~ ; a2 partial ======
        {
            u64t acc[SAMP];
            #pragma unroll
            for (int s = 0; s < SAMP; s++) acc[s] = 0ull;
            const float* wzrow = &sm->wz1[j * WZ1_S + 32 * q];
            const int kb = 32 * q;
            #pragma unroll
            for (int kq = 0; kq < 32; kq += 4) {
                ulonglong2 w = *(const ulonglong2*)(wzrow + kq);
                #pragma unroll
                for (int s = 0; s < SAMP; s++) {
                    ulonglong2 hv = *(const ulonglong2*)&sm->h0v[s][kb + kq];
                    fma2(acc[s], w.x, hv.x);
                    fma2(acc[s], w.y, hv.y);
                }
            }
            const float* wyrow = &sm->wy1[j * WY_S + 16 * q];
            const int cb = 16 * q;
            #pragma unroll
            for (int cq = 0; cq < 16; cq += 4) {
                ulonglong2 w = *(const ulonglong2*)(wyrow + cq);
                #pragma unroll
                for (int s = 0; s < SAMP; s++) {
                    ulonglong2 xv = *(const ulonglong2*)&sm->x1[s][cb + cq];
                    fma2(acc[s], w.x, xv.x);
                    fma2(acc[s], w.y, xv.y);
                }
            }
            #pragma unroll
            for (int s = 0; s < SAMP; s++)
                sm->scratch[q * 1024 + s * HH + j] = rsum2(acc[s]);
            __syncthreads();
            const float wz2j = sm->wz2[j];
            float pv[2];
            #pragma unroll
            for (int t = 0; t < 2; t++) {
                int s = 2 * q + t;
                float a = sm->scratch[0 * 1024 + s * HH + j]
                        + sm->scratch[1 * 1024 + s * HH + j]
                        + sm->scratch[2 * 1024 + s * HH + j]
                        + sm->scratch[3 * 1024 + s * HH + j] + sm->by1[j];
                float e   = __expf(-fabsf(a));
                float inv = __fdividef(1.0f, 1.0f + e);
                float sg  = (a >= 0.0f) ? inv : e * inv;
                sm->s1u[s][j] = wz2j * sg;                               // u~
                pv[t] = wz2j * (fmaxf(a, 0.0f) + __logf(1.0f + e));      // wz2*h1
            }
            #pragma unroll
            for (int off = 16; off; off >>= 1) {
                pv[0] += __shfl_down_sync(0xffffffffu, pv[0], off);
                pv[1] += __shfl_down_sync(0xffffffffu, pv[1], off);
            }
            if (lane == 0) {   // 4 warps per sample-pair contribute
                atomicAdd(&sm->a2[2 * q],     pv[0]);
                atomicAdd(&sm->a2[2 * q + 1], pv[1]);
            }
        }
        __syncthreads();

        // ============ stage 3: s2 = sigmoid(a2 + Wy2.x1 + by2) ============
        if (warp < SAMP) {
            float part = sm->wy2[lane]      * sm->x1[warp][lane]
                       + sm->wy2[lane + 32] * sm->x1[warp][lane + 32];
            #pragma unroll
            for (int off = 16; off; off >>= 1)
                part += __shfl_down_sync(0xffffffffu, part, off);
            if (lane == 0) {
                float a   = sm->a2[warp] + part + sm->by2;
                float e   = __expf(-fabsf(a));
                float inv = __fdividef(1.0f, 1.0f + e);
                sm->s2[warp] = (a >= 0.0f) ? inv : e * inv;
            }
        }
        __syncthreads();

        // ========= stage 5: v~_k = s0_k * sum_j u~_j wz1[j][k] =========
        {
            u64t acc[SAMP];
            #pragma unroll
            for (int s = 0; s < SAMP; s++) acc[s] = 0ull;
            const int jb = 32 * q;
            #pragma unroll
            for (int jq = 0; jq < 32; jq += 4) {
                const float* col = &sm->wz1[(jb + jq) * WZ1_S + j];
                u64t wA = pk2(col[0],         col[WZ1_S]);
                u64t wB = pk2(col[2 * WZ1_S], col[3 * WZ1_S]);
                #pragma unroll
                for (int s = 0; s < SAMP; s++) {
                    ulonglong2 uv = *(const ulonglong2*)&sm->s1u[s][jb + jq];
                    fma2(acc[s], wA, uv.x);
                    fma2(acc[s], wB, uv.y);
                }
            }
            #pragma unroll
            for (int s = 0; s < SAMP; s++)
                sm->scratch[q * 1024 + s * HH + j] = rsum2(acc[s]);
            __syncthreads();
            #pragma unroll
            for (int t = 0; t < 2; t++) {
                int s = 2 * q + t;
                float v = sm->scratch[0 * 1024 + s * HH + j]
                        + sm->scratch[1 * 1024 + s * HH + j]
                        + sm->scratch[2 * 1024 + s * HH + j]
                        + sm->scratch[3 * 1024 + s * HH + j];
                sm->h0v[s][j] = v * sm->s0[s][j];
            }
        }
        __syncthreads();

        // == stage 6: g = s2*(v~ Wy0 + u~ Wy1 + Wy2) + x1 ; update ; norm ==
        {
            u64t acc[SAMP];
            #pragma unroll
            for (int s = 0; s < SAMP; s++) acc[s] = 0ull;
            const int kb = 16 * o6;
            #pragma unroll
            for (int kq = 0; kq < 16; kq += 4) {
                int k = kb + kq;
                const float* c0 = &sm->wy0[k * WY_S + c6];
                const float* c1 = &sm->wy1[k * WY_S + c6];
                u64t w0A = pk2(c0[0],        c0[WY_S]);
                u64t w0B = pk2(c0[2 * WY_S], c0[3 * WY_S]);
                u64t w1A = pk2(c1[0],        c1[WY_S]);
                u64t w1B = pk2(c1[2 * WY_S], c1[3 * WY_S]);
                #pragma unroll
                for (int s = 0; s < SAMP; s++) {
                    ulonglong2 vv = *(const ulonglong2*)&sm->h0v[s][k];
                    ulonglong2 uu = *(const ulonglong2*)&sm->s1u[s][k];
                    fma2(acc[s], w0A, vv.x);
                    fma2(acc[s], w0B, vv.y);
                    fma2(acc[s], w1A, uu.x);
                    fma2(acc[s], w1B, uu.y);
                }
            }
            #pragma unroll
            for (int s = 0; s < SAMP; s++)
                sm->scratch[o6 * 512 + s * CC + c6] = rsum2(acc[s]);
            __syncthreads();

            const float step = __fdividef(2.0f, (float)(it + 1));
            const int s = o6;                      // one sample per eighth
            float g = 0.0f;
            #pragma unroll
            for (int oo = 0; oo < 8; oo++)
                g += sm->scratch[oo * 512 + s * CC + c6];
            float x1v = sm->x1[s][c6];
            g = sm->s2[s] * (g + sm->wy2[c6]) + x1v;
            float d = sm->z[s][c6] - g;
            sm->x1[s][c6] = x1v + step * d;
            float d2 = d * d;
            #pragma unroll
            for (int off = 16; off; off >>= 1)
                d2 += __shfl_down_sync(0xffffffffu, d2, off);
            if (lane == 0) atomicAdd(&sm->nrm2[s], d2);   // 2 warps per sample
        }
        __syncthreads();

        // ==== merged error reduction + grid barrier (per-iter slots) ====
        if (tid == 0) {
            float sum = 0.0f;
            #pragma unroll
            for (int s = 0; s < SAMP; s++) sum += sqrtf(sm->nrm2[s]);
            atomicAdd(&g_err[it], sum);
            __threadfence();
            unsigned int n = atomicAdd(&g_cnt[it], 1u) + 1u;
            while (n < (unsigned)NBLOCKS) {
                __nanosleep(32);
                n = *((volatile unsigned int*)&g_cnt[it]);
            }
            sm->flag = (*((volatile float*)&g_err[it]) < TOLV * 1024.0f) ? 1 : 0;
        }
        __syncthreads();
        if (sm->flag) break;   // done flips; remaining iterations are no-ops
    }

    // ---- output: x1 + CONVEX*z ----
    for (int idx = tid; idx < SAMP * CC; idx += NTHREADS) {
        int s = idx >> 6, c2 = idx & 63;
        out[sbase * CC + idx] = sm->x1[s][c2] + sm->z[s][c2];
    }
}

extern "C" void kernel_launch(void* const* d_in, const int* in_sizes, int n_in,
                              void* d_out, int out_size) {
    (void)in_sizes; (void)n_in; (void)out_size;
    cudaFuncSetAttribute(blnn_kernel,
                         cudaFuncAttributeMaxDynamicSharedMemorySize,
                         (int)sizeof(Smem));
    blnn_kernel<<<NBLOCKS, NTHREADS, sizeof(Smem)>>>(
        (const float*)d_in[0], (const float*)d_in[1], (const float*)d_in[2],
        (const float*)d_in[3], (const float*)d_in[4], (const float*)d_in[5],
        (const float*)d_in[6], (const float*)d_in[7], (const float*)d_in[8],
        (float*)d_out);
}